// round 14
// baseline (speedup 1.0000x reference)
#include <cuda_runtime.h>
#include <cuda_fp16.h>
#include <cstdint>
#include <cmath>

typedef unsigned int u32;

#define NT 384
#define TS 384
#define ROWB 144          // bytes per activation/weight row (72 fp16)

// ---- smem byte offsets ----
// NOTE: SM_CW3 spans [41616, 42384). SM_AH MUST start >= 42384 (R9 bug).
#define SM_WD1H 0
#define SM_WD2H 9216
#define SM_WD3H 18432
#define SM_WC1H 20736
#define SM_WC2H 29952
#define SM_DB1  39168
#define SM_DB2  39424
#define SM_DB3  39680
#define SM_CB1  39744
#define SM_CB2  40000
#define SM_CB3  40256
#define SM_RW1  40272
#define SM_RB1  40464
#define SM_CW3  41616     // ends 42384
#define SM_AH   42496     // 384 rows x 144B fp16 (hi)   [42496..97792)
#define SM_AL   97792     // 384 rows x 144B fp16 (lo)   [97792..153088)
#define SM_OUT  153088    // 384 rows x 19 fp32 staging  [153088..182272)
#define SMEM_BYTES 182272

__device__ __forceinline__ u32 pk2h(float vlo, float vhi) {
    u32 r; asm("cvt.rn.f16x2.f32 %0, %1, %2;" : "=r"(r) : "f"(vhi), "f"(vlo));
    return r;
}
__device__ __forceinline__ float2 up2h(u32 p) {
    float lo, hi;
    asm("{ .reg .f16 l, h; mov.b32 {l, h}, %2; cvt.f32.f16 %0, l; cvt.f32.f16 %1, h; }"
        : "=f"(lo), "=f"(hi) : "r"(p));
    return make_float2(lo, hi);
}
__device__ __forceinline__ void ldsm4(u32 addr, u32& r0, u32& r1, u32& r2, u32& r3) {
    asm volatile("ldmatrix.sync.aligned.m8n8.x4.shared.b16 {%0,%1,%2,%3}, [%4];"
                 : "=r"(r0), "=r"(r1), "=r"(r2), "=r"(r3) : "r"(addr) : "memory");
}
__device__ __forceinline__ void mmah(float* c, u32 a0, u32 a1, u32 a2, u32 a3,
                                     u32 b0, u32 b1) {
    asm("mma.sync.aligned.m16n8k16.row.col.f32.f16.f16.f32 "
        "{%0,%1,%2,%3},{%4,%5,%6,%7},{%8,%9},{%0,%1,%2,%3};"
        : "+f"(c[0]), "+f"(c[1]), "+f"(c[2]), "+f"(c[3])
        : "r"(a0), "r"(a1), "r"(a2), "r"(a3), "r"(b0), "r"(b1));
}

// GEMM: acc[2*NTL][4] += fp16-2-term( A[warp rows] * W^T ).  All smem.
template<int KT, int NTL>
__device__ __forceinline__ void do_gemm(u32 aH, u32 aL, u32 wH,
                                        int lane, int warp, float (*acc)[4]) {
#pragma unroll
    for (int t = 0; t < 2 * NTL; ++t) {
        acc[t][0] = 0.f; acc[t][1] = 0.f; acc[t][2] = 0.f; acc[t][3] = 0.f;
    }
    const u32 aOff = (u32)(warp * 32 + (lane & 15)) * ROWB + (u32)(lane >> 4) * 16;
    const u32 bOff = (u32)((lane & 7) + ((lane >> 4) & 1) * 8) * ROWB
                   + (u32)((lane >> 3) & 1) * 16;
#pragma unroll
    for (int kt = 0; kt < KT; ++kt) {
        u32 h00,h01,h02,h03, h10,h11,h12,h13;
        u32 l00,l01,l02,l03, l10,l11,l12,l13;
        ldsm4(aH + aOff + kt * 32,             h00, h01, h02, h03);
        ldsm4(aH + aOff + 16 * ROWB + kt * 32, h10, h11, h12, h13);
        ldsm4(aL + aOff + kt * 32,             l00, l01, l02, l03);
        ldsm4(aL + aOff + 16 * ROWB + kt * 32, l10, l11, l12, l13);
        if constexpr (NTL >= 4) {
#pragma unroll
            for (int pp = 0; pp < NTL / 4; ++pp) {
                u32 b0, b1, b2, b3, c0, c1, c2, c3;
                ldsm4(wH + bOff + (u32)((2*pp)   * 16) * ROWB + kt * 32, b0, b1, b2, b3);
                ldsm4(wH + bOff + (u32)((2*pp+1) * 16) * ROWB + kt * 32, c0, c1, c2, c3);
                mmah(acc[4*pp],           h00, h01, h02, h03, b0, b1);
                mmah(acc[4*pp + 1],       h00, h01, h02, h03, b2, b3);
                mmah(acc[NTL + 4*pp],     h10, h11, h12, h13, b0, b1);
                mmah(acc[NTL + 4*pp + 1], h10, h11, h12, h13, b2, b3);
                mmah(acc[4*pp + 2],       h00, h01, h02, h03, c0, c1);
                mmah(acc[4*pp + 3],       h00, h01, h02, h03, c2, c3);
                mmah(acc[NTL + 4*pp + 2], h10, h11, h12, h13, c0, c1);
                mmah(acc[NTL + 4*pp + 3], h10, h11, h12, h13, c2, c3);
                mmah(acc[4*pp],           l00, l01, l02, l03, b0, b1);
                mmah(acc[4*pp + 1],       l00, l01, l02, l03, b2, b3);
                mmah(acc[NTL + 4*pp],     l10, l11, l12, l13, b0, b1);
                mmah(acc[NTL + 4*pp + 1], l10, l11, l12, l13, b2, b3);
                mmah(acc[4*pp + 2],       l00, l01, l02, l03, c0, c1);
                mmah(acc[4*pp + 3],       l00, l01, l02, l03, c2, c3);
                mmah(acc[NTL + 4*pp + 2], l10, l11, l12, l13, c0, c1);
                mmah(acc[NTL + 4*pp + 3], l10, l11, l12, l13, c2, c3);
            }
        } else {
#pragma unroll
            for (int p = 0; p < NTL / 2; ++p) {
                u32 b0, b1, b2, b3;
                ldsm4(wH + bOff + (u32)(p * 16) * ROWB + kt * 32, b0, b1, b2, b3);
                mmah(acc[2*p],           h00, h01, h02, h03, b0, b1);
                mmah(acc[2*p + 1],       h00, h01, h02, h03, b2, b3);
                mmah(acc[NTL + 2*p],     h10, h11, h12, h13, b0, b1);
                mmah(acc[NTL + 2*p + 1], h10, h11, h12, h13, b2, b3);
                mmah(acc[2*p],           l00, l01, l02, l03, b0, b1);
                mmah(acc[2*p + 1],       l00, l01, l02, l03, b2, b3);
                mmah(acc[NTL + 2*p],     l10, l11, l12, l13, b0, b1);
                mmah(acc[NTL + 2*p + 1], l10, l11, l12, l13, b2, b3);
            }
        }
    }
}

// Epilogue: bias + relu, write back as fp16 hi/lo rows.
template<int NTL>
__device__ __forceinline__ void epi_f16(const float (*acc)[4], const float* bias,
                                        char* smc, int lane, int warp) {
    const int r0 = warp * 32 + (lane >> 2);
    const int cb = (lane & 3) * 2;
#pragma unroll
    for (int mt = 0; mt < 2; ++mt) {
#pragma unroll
        for (int nt = 0; nt < NTL; ++nt) {
            const int c = 8 * nt + cb;
            const float b0 = bias[c], b1 = bias[c + 1];
            const float* a = acc[mt * NTL + nt];
            float v0 = fmaxf(a[0] + b0, 0.f), v1 = fmaxf(a[1] + b1, 0.f);
            float v2 = fmaxf(a[2] + b0, 0.f), v3 = fmaxf(a[3] + b1, 0.f);
            const int rA = r0 + 16 * mt, rB = rA + 8;
            u32 h01 = pk2h(v0, v1), h23 = pk2h(v2, v3);
            float2 f01 = up2h(h01), f23 = up2h(h23);
            u32 l01 = pk2h(v0 - f01.x, v1 - f01.y);
            u32 l23 = pk2h(v2 - f23.x, v3 - f23.y);
            *(u32*)(smc + SM_AH + rA * ROWB + c * 2) = h01;
            *(u32*)(smc + SM_AH + rB * ROWB + c * 2) = h23;
            *(u32*)(smc + SM_AL + rA * ROWB + c * 2) = l01;
            *(u32*)(smc + SM_AL + rB * ROWB + c * 2) = l23;
        }
    }
}

// Write activation row chunks [ch0, ch1) of 8 cols each; v indexed from 0.
__device__ __forceinline__ void write_row_chunks(char* smc, int s, const float* v,
                                                 int ch0, int ch1) {
    for (int ch = ch0; ch < ch1; ++ch) {
        u32 h[4], l[4];
#pragma unroll
        for (int q = 0; q < 4; ++q) {
            float x0 = v[8 * (ch - ch0) + 2 * q], x1 = v[8 * (ch - ch0) + 2 * q + 1];
            u32 hp = pk2h(x0, x1);
            float2 f = up2h(hp);
            h[q] = hp;
            l[q] = pk2h(x0 - f.x, x1 - f.y);
        }
        *(uint4*)(smc + SM_AH + s * ROWB + ch * 16) = make_uint4(h[0], h[1], h[2], h[3]);
        *(uint4*)(smc + SM_AL + s * ROWB + ch * 16) = make_uint4(l[0], l[1], l[2], l[3]);
    }
}

// fp32 W[k][n] (global) -> smem [n][72] fp16, K padded to 64.
__device__ void prep_B(char* smc, const float* W, int Kreal, int Nrows, int stride,
                       int offH) {
    for (int idx = threadIdx.x; idx < Nrows * 64; idx += NT) {
        int nr = idx >> 6, k = idx & 63;
        float x = (k < Kreal) ? __ldg(W + k * stride + nr) : 0.0f;
        u32 p = pk2h(x, x);
        *(unsigned short*)(smc + offH + nr * ROWB + k * 2) = (unsigned short)(p & 0xffffu);
    }
}

// Color-L1 weights, folded + K-permuted to the new cin order:
//   k' 0..31  : app j=k'        -> cw1 row 31+k'
//   k' 32..46 : geo g=k'-32     -> cw1 row g
//   k' 47..62 : dir-hidden t    -> sum_j rw2[t][j] * cw1[15+j]
//   k' 63     : 0 (pad)
__device__ void prep_CW1_folded(char* smc, const float* cw1, const float* rw2,
                                int offH) {
    for (int idx = threadIdx.x; idx < 64 * 64; idx += NT) {
        int nr = idx >> 6, k = idx & 63;
        float x;
        if (k < 32) {
            x = __ldg(cw1 + (31 + k) * 64 + nr);
        } else if (k < 47) {
            x = __ldg(cw1 + (k - 32) * 64 + nr);
        } else if (k < 63) {
            const int t = k - 47;
            float s = 0.0f;
#pragma unroll
            for (int j = 0; j < 16; ++j)
                s = fmaf(__ldg(rw2 + t * 16 + j), __ldg(cw1 + (15 + j) * 64 + nr), s);
            x = s;
        } else {
            x = 0.0f;
        }
        u32 p = pk2h(x, x);
        *(unsigned short*)(smc + offH + nr * ROWB + k * 2) = (unsigned short)(p & 0xffffu);
    }
}

__device__ void cpyf(char* smc, int off, const float* src, int nf) {
    float* d = (float*)(smc + off);
    for (int t = threadIdx.x; t < nf; t += NT) d[t] = __ldg(src + t);
}

struct ResArr { int r[16]; };

__global__ void __launch_bounds__(NT, 1) nerf_h9_kernel(
    const float* __restrict__ rs, const float* __restrict__ dirs,
    const int*   __restrict__ cam, const float* __restrict__ aabb,
    const float* __restrict__ ht,
    const float* __restrict__ rw1, const float* __restrict__ rb1,
    const float* __restrict__ rw2, const float* __restrict__ rb2,
    const float* __restrict__ dw1, const float* __restrict__ db1,
    const float* __restrict__ dw2, const float* __restrict__ db2,
    const float* __restrict__ dw3, const float* __restrict__ db3,
    const float* __restrict__ cw1, const float* __restrict__ cb1,
    const float* __restrict__ cw2, const float* __restrict__ cb2,
    const float* __restrict__ cw3, const float* __restrict__ cb3,
    const float* __restrict__ app,
    float* __restrict__ out, int n, ResArr RA)
{
    extern __shared__ __align__(128) char smc[];
    u32 sb;
    asm("{ .reg .u64 t; cvta.to.shared.u64 t, %1; cvt.u32.u64 %0, t; }"
        : "=r"(sb) : "l"(smc));

    prep_B(smc, dw1, 32, 64, 64, SM_WD1H);
    prep_B(smc, dw2, 64, 64, 64, SM_WD2H);
    prep_B(smc, dw3, 64, 16, 16, SM_WD3H);
    prep_CW1_folded(smc, cw1, rw2, SM_WC1H);
    prep_B(smc, cw2, 64, 64, 64, SM_WC2H);
    cpyf(smc, SM_DB1, db1, 64);  cpyf(smc, SM_DB2, db2, 64);
    cpyf(smc, SM_DB3, db3, 16);
    // cb1' = cb1 + rb2 @ cw1[15:31]  (bias independent of K order)
    if (threadIdx.x < 64) {
        const int t = threadIdx.x;
        float s = __ldg(cb1 + t);
#pragma unroll
        for (int j = 0; j < 16; ++j)
            s = fmaf(__ldg(rb2 + j), __ldg(cw1 + (15 + j) * 64 + t), s);
        ((float*)(smc + SM_CB1))[t] = s;
    }
    cpyf(smc, SM_CB2, cb2, 64);  cpyf(smc, SM_CB3, cb3, 3);
    cpyf(smc, SM_RW1, rw1, 48);  cpyf(smc, SM_RB1, rb1, 16);
    cpyf(smc, SM_CW3, cw3, 192);
    __syncthreads();

    const int tid = threadIdx.x, lane = tid & 31, warp = tid >> 5;
    const u32 AHu = sb + SM_AH, ALu = sb + SM_AL;

    const float a0x = __ldg(aabb + 0), a0y = __ldg(aabb + 1), a0z = __ldg(aabb + 2);
    const float ddx = __ldg(aabb + 3) - a0x;
    const float ddy = __ldg(aabb + 4) - a0y;
    const float ddz = __ldg(aabb + 5) - a0z;
    const float2* htp = (const float2*)ht;
    const float* sDB1 = (const float*)(smc + SM_DB1);
    const float* sDB2 = (const float*)(smc + SM_DB2);
    const float* sDB3 = (const float*)(smc + SM_DB3);
    const float* sCB1 = (const float*)(smc + SM_CB1);
    const float* sCB2 = (const float*)(smc + SM_CB2);
    const float* sCB3 = (const float*)(smc + SM_CB3);
    const float* sRW1 = (const float*)(smc + SM_RW1);
    const float* sRB1 = (const float*)(smc + SM_RB1);
    const float* sCW3 = (const float*)(smc + SM_CW3);
    float* sOUT = (float*)(smc + SM_OUT);

    const int ntiles = (n + TS - 1) / TS;

    for (int tile = blockIdx.x; tile < ntiles; tile += gridDim.x) {
        const int i0 = tile * TS;
        int i = i0 + tid; if (i >= n) i = n - 1;

        // ---- hash encode (exact fp32) -> A row (32 cols) ----
        {
            float ev[32];
            const float px = fminf(fmaxf((__ldg(rs + 3*i + 0) - a0x) / ddx, 0.f), 1.f);
            const float py = fminf(fmaxf((__ldg(rs + 3*i + 1) - a0y) / ddy, 0.f), 1.f);
            const float pz = fminf(fmaxf((__ldg(rs + 3*i + 2) - a0z) / ddz, 0.f), 1.f);
#pragma unroll
            for (int l = 0; l < 16; ++l) {
                const int r = RA.r[l];
                const float rf = (float)(r - 1);
                int cx = (int)floorf(px * rf);
                int cy = (int)floorf(py * rf);
                int cz = (int)floorf(pz * rf);
                cx = min(max(cx, 0), r - 1);
                cy = min(max(cy, 0), r - 1);
                cz = min(max(cz, 0), r - 1);
                const unsigned h = ((unsigned)cx + (unsigned)cy * 2481u
                                    + (unsigned)cz * 1941u) & 4095u;
                const float2 f = __ldg(htp + l * 4096 + h);
                ev[2*l] = f.x; ev[2*l + 1] = f.y;
            }
            write_row_chunks(smc, tid, ev, 0, 4);
        }
        __syncwarp();

        float acc[16][4];
        // ---- density L1 (K=32) ----
        do_gemm<2, 8>(AHu, ALu, sb + SM_WD1H, lane, warp, acc);
        __syncwarp();
        epi_f16<8>(acc, sDB1, smc, lane, warp);
        __syncwarp();
        // ---- density L2 (K=64) ----
        do_gemm<4, 8>(AHu, ALu, sb + SM_WD2H, lane, warp, acc);
        __syncwarp();
        epi_f16<8>(acc, sDB2, smc, lane, warp);
        __syncwarp();
        // ---- density L3 (64 -> 16) -> sOUT cols 3..18 (raw dfeat) ----
        do_gemm<4, 2>(AHu, ALu, sb + SM_WD3H, lane, warp, acc);
        __syncwarp();
        {
            const int cb = (lane & 3) * 2;
#pragma unroll
            for (int mt = 0; mt < 2; ++mt)
#pragma unroll
                for (int nt = 0; nt < 2; ++nt) {
                    const int c = 8 * nt + cb;
                    const float b0 = sDB3[c], b1 = sDB3[c + 1];
                    const float* a = acc[mt * 2 + nt];
                    const int rA = warp * 32 + 16 * mt + (lane >> 2), rB = rA + 8;
                    sOUT[rA * 19 + 3 + c] = a[0] + b0;
                    sOUT[rA * 19 + 4 + c] = a[1] + b1;
                    sOUT[rB * 19 + 3 + c] = a[2] + b0;
                    sOUT[rB * 19 + 4 + c] = a[3] + b1;
                }
        }
        __syncwarp();

        // ---- build cin:  cols 0..31 = app (warp-cooperative, 1 line/LDG),
        //                  cols 32..46 = geo, 47..62 = dir-hidden, 63 = pad ----
        float df0;
        {
            const int ci = __ldg(cam + i);
            // warp-cooperative appearance load: sample s's row read by all lanes
            const char* smAH = smc + SM_AH;
            const char* smAL = smc + SM_AL;
#pragma unroll 4
            for (int s = 0; s < 32; ++s) {
                const int cis = __shfl_sync(0xffffffffu, ci, s);
                const float v = __ldg(app + (size_t)cis * 32 + lane);
                const __half hh = __float2half(v);
                const __half hl = __float2half(v - __half2float(hh));
                const int row = warp * 32 + s;
                *(__half*)(smAH + row * ROWB + lane * 2) = hh;
                *(__half*)(smAL + row * ROWB + lane * 2) = hl;
            }
            // own-sample geo + dir layer-1 -> cols 32..63
            const float* drow = sOUT + (warp * 32 + lane) * 19 + 3;
            float cin2[32];
            df0 = drow[0];
#pragma unroll
            for (int j = 0; j < 15; ++j) cin2[j] = drow[1 + j];
            const float dv[3] = { __ldg(dirs + 3*i + 0), __ldg(dirs + 3*i + 1),
                                  __ldg(dirs + 3*i + 2) };
#pragma unroll
            for (int j = 0; j < 16; ++j) {
                float a = sRB1[j];
#pragma unroll
                for (int k = 0; k < 3; ++k)
                    a = fmaf(dv[k], sRW1[k*16 + j], a);
                cin2[15 + j] = fmaxf(a, 0.0f);
            }
            cin2[31] = 0.0f;
            write_row_chunks(smc, tid, cin2, 4, 8);
        }
        __syncwarp();
        // ---- color L1 (K=64, folded + permuted weights, cb1') ----
        do_gemm<4, 8>(AHu, ALu, sb + SM_WC1H, lane, warp, acc);
        __syncwarp();
        epi_f16<8>(acc, sCB1, smc, lane, warp);
        __syncwarp();
        // ---- color L2 (K=64); final 64->3 straight from accumulators ----
        do_gemm<4, 8>(AHu, ALu, sb + SM_WC2H, lane, warp, acc);
        __syncwarp();
        {
            const int cb = (lane & 3) * 2;
#pragma unroll
            for (int mt = 0; mt < 2; ++mt)
#pragma unroll
                for (int nt = 0; nt < 8; ++nt) {
                    const int c = 8 * nt + cb;
                    float* a = acc[mt * 8 + nt];
                    a[0] = fmaxf(a[0] + sCB2[c], 0.f);
                    a[1] = fmaxf(a[1] + sCB2[c + 1], 0.f);
                    a[2] = fmaxf(a[2] + sCB2[c], 0.f);
                    a[3] = fmaxf(a[3] + sCB2[c + 1], 0.f);
                }
            float w3[8][2][3];
#pragma unroll
            for (int nt = 0; nt < 8; ++nt)
#pragma unroll
                for (int e = 0; e < 2; ++e) {
                    const int c = 8 * nt + cb + e;
#pragma unroll
                    for (int j = 0; j < 3; ++j) w3[nt][e][j] = sCW3[c * 3 + j];
                }
            float s[4][3];
#pragma unroll
            for (int v = 0; v < 4; ++v)
#pragma unroll
                for (int j = 0; j < 3; ++j) s[v][j] = 0.f;
#pragma unroll
            for (int mt = 0; mt < 2; ++mt)
#pragma unroll
                for (int h = 0; h < 2; ++h)
#pragma unroll
                    for (int nt = 0; nt < 8; ++nt)
#pragma unroll
                        for (int e = 0; e < 2; ++e) {
                            const float x = acc[mt * 8 + nt][2 * h + e];
#pragma unroll
                            for (int j = 0; j < 3; ++j)
                                s[mt * 2 + h][j] = fmaf(x, w3[nt][e][j],
                                                        s[mt * 2 + h][j]);
                        }
#pragma unroll
            for (int v = 0; v < 4; ++v)
#pragma unroll
                for (int j = 0; j < 3; ++j) {
                    s[v][j] += __shfl_xor_sync(0xffffffffu, s[v][j], 1);
                    s[v][j] += __shfl_xor_sync(0xffffffffu, s[v][j], 2);
                }
            const int q = lane & 3;
            const int row = warp * 32 + 16 * (q >> 1) + 8 * (q & 1) + (lane >> 2);
            const float r0 = s[q][0], r1 = s[q][1], r2 = s[q][2];
            sOUT[row * 19 + 0] = 1.0f / (1.0f + expf(-(r0 + sCB3[0])));
            sOUT[row * 19 + 1] = 1.0f / (1.0f + expf(-(r1 + sCB3[1])));
            sOUT[row * 19 + 2] = 1.0f / (1.0f + expf(-(r2 + sCB3[2])));
            sOUT[(warp * 32 + lane) * 19 + 3] = fmaxf(df0, 0.0f);
        }
        __syncwarp();
        // ---- linear coalesced store: staging layout == output layout ----
        {
            const int m = min(TS, n - i0);
            const int vw = min(32, m - warp * 32);
            if (vw > 0) {
                float* gbase = out + (size_t)(i0 + warp * 32) * 19;
                const float* sbase = sOUT + (warp * 32) * 19;
                if (vw == 32) {
                    const float4* s4 = (const float4*)sbase;
                    float4* g4 = (float4*)gbase;
#pragma unroll
                    for (int j = 0; j < 5; ++j) {
                        int idx = lane + j * 32;
                        if (idx < 152) g4[idx] = s4[idx];
                    }
                } else {
                    for (int j = lane; j < vw * 19; j += 32) gbase[j] = sbase[j];
                }
            }
        }
        __syncwarp();
    }
}

extern "C" void kernel_launch(void* const* d_in, const int* in_sizes, int n_in,
                              void* d_out, int out_size) {
    const float* rs   = (const float*)d_in[0];
    const float* dirs = (const float*)d_in[1];
    const int*   cam  = (const int*)d_in[2];
    const float* aabb = (const float*)d_in[3];
    const float* ht   = (const float*)d_in[4];
    const float* rw1  = (const float*)d_in[5];
    const float* rb1  = (const float*)d_in[6];
    const float* rw2  = (const float*)d_in[7];
    const float* rb2  = (const float*)d_in[8];
    const float* dw1  = (const float*)d_in[9];
    const float* db1  = (const float*)d_in[10];
    const float* dw2  = (const float*)d_in[11];
    const float* db2  = (const float*)d_in[12];
    const float* dw3  = (const float*)d_in[13];
    const float* db3  = (const float*)d_in[14];
    const float* cw1  = (const float*)d_in[15];
    const float* cb1  = (const float*)d_in[16];
    const float* cw2  = (const float*)d_in[17];
    const float* cb2  = (const float*)d_in[18];
    const float* cw3  = (const float*)d_in[19];
    const float* cb3  = (const float*)d_in[20];
    const float* app  = (const float*)d_in[21];
    float* out = (float*)d_out;

    const int n = in_sizes[0] / 3;

    ResArr ra;
    double growth = exp((log(2048.0) - log(16.0)) / 15.0);
    for (int i = 0; i < 16; ++i)
        ra.r[i] = (int)(16.0 * pow(growth, (double)i));

    cudaFuncSetAttribute(nerf_h9_kernel,
                         cudaFuncAttributeMaxDynamicSharedMemorySize, SMEM_BYTES);

    dim3 grid(148), block(NT);   // 1 CTA/SM persistent, 12 warps, warp-independent
    nerf_h9_kernel<<<grid, block, SMEM_BYTES>>>(
        rs, dirs, cam, aabb, ht,
        rw1, rb1, rw2, rb2,
        dw1, db1, dw2, db2, dw3, db3,
        cw1, cb1, cw2, cb2, cw3, cb3,
        app, out, n, ra);
}

// round 15
// speedup vs baseline: 1.0606x; 1.0606x over previous
#include <cuda_runtime.h>
#include <cuda_fp16.h>
#include <cstdint>
#include <cmath>

typedef unsigned int u32;

#define NT 384
#define TS 384
#define ROWB 144          // bytes per activation/weight row (72 fp16)

// ---- smem byte offsets ----
// NOTE: SM_CW3 spans [41616, 42384). SM_AH MUST start >= 42384 (R9 bug:
// overlap corrupted cw3). Layout identical to R12 (best known).
#define SM_WD1H 0
#define SM_WD2H 9216
#define SM_WD3H 18432
#define SM_WC1H 20736
#define SM_WC2H 29952
#define SM_DB1  39168
#define SM_DB2  39424
#define SM_DB3  39680
#define SM_CB1  39744
#define SM_CB2  40000
#define SM_CB3  40256
#define SM_RW1  40272
#define SM_RB1  40464
#define SM_CW3  41616     // ends 42384
#define SM_AH   42496     // 384 rows x 144B fp16 (hi)   [42496..97792)
#define SM_AL   97792     // 384 rows x 144B fp16 (lo)   [97792..153088)
#define SM_OUT  153088    // 384 rows x 19 fp32 staging  [153088..182272)
#define SMEM_BYTES 182272

__device__ __forceinline__ u32 pk2h(float vlo, float vhi) {
    u32 r; asm("cvt.rn.f16x2.f32 %0, %1, %2;" : "=r"(r) : "f"(vhi), "f"(vlo));
    return r;
}
__device__ __forceinline__ float2 up2h(u32 p) {
    float lo, hi;
    asm("{ .reg .f16 l, h; mov.b32 {l, h}, %2; cvt.f32.f16 %0, l; cvt.f32.f16 %1, h; }"
        : "=f"(lo), "=f"(hi) : "r"(p));
    return make_float2(lo, hi);
}
__device__ __forceinline__ void ldsm4(u32 addr, u32& r0, u32& r1, u32& r2, u32& r3) {
    asm volatile("ldmatrix.sync.aligned.m8n8.x4.shared.b16 {%0,%1,%2,%3}, [%4];"
                 : "=r"(r0), "=r"(r1), "=r"(r2), "=r"(r3) : "r"(addr) : "memory");
}
__device__ __forceinline__ void mmah(float* c, u32 a0, u32 a1, u32 a2, u32 a3,
                                     u32 b0, u32 b1) {
    asm("mma.sync.aligned.m16n8k16.row.col.f32.f16.f16.f32 "
        "{%0,%1,%2,%3},{%4,%5,%6,%7},{%8,%9},{%0,%1,%2,%3};"
        : "+f"(c[0]), "+f"(c[1]), "+f"(c[2]), "+f"(c[3])
        : "r"(a0), "r"(a1), "r"(a2), "r"(a3), "r"(b0), "r"(b1));
}

// GEMM: acc[2*NTL][4] += fp16-2-term( A[warp rows] * W^T ).  All smem.
template<int KT, int NTL>
__device__ __forceinline__ void do_gemm(u32 aH, u32 aL, u32 wH,
                                        int lane, int warp, float (*acc)[4]) {
#pragma unroll
    for (int t = 0; t < 2 * NTL; ++t) {
        acc[t][0] = 0.f; acc[t][1] = 0.f; acc[t][2] = 0.f; acc[t][3] = 0.f;
    }
    const u32 aOff = (u32)(warp * 32 + (lane & 15)) * ROWB + (u32)(lane >> 4) * 16;
    const u32 bOff = (u32)((lane & 7) + ((lane >> 4) & 1) * 8) * ROWB
                   + (u32)((lane >> 3) & 1) * 16;
#pragma unroll
    for (int kt = 0; kt < KT; ++kt) {
        u32 h00,h01,h02,h03, h10,h11,h12,h13;
        u32 l00,l01,l02,l03, l10,l11,l12,l13;
        ldsm4(aH + aOff + kt * 32,             h00, h01, h02, h03);
        ldsm4(aH + aOff + 16 * ROWB + kt * 32, h10, h11, h12, h13);
        ldsm4(aL + aOff + kt * 32,             l00, l01, l02, l03);
        ldsm4(aL + aOff + 16 * ROWB + kt * 32, l10, l11, l12, l13);
        if constexpr (NTL >= 4) {
#pragma unroll
            for (int pp = 0; pp < NTL / 4; ++pp) {
                u32 b0, b1, b2, b3, c0, c1, c2, c3;
                ldsm4(wH + bOff + (u32)((2*pp)   * 16) * ROWB + kt * 32, b0, b1, b2, b3);
                ldsm4(wH + bOff + (u32)((2*pp+1) * 16) * ROWB + kt * 32, c0, c1, c2, c3);
                mmah(acc[4*pp],           h00, h01, h02, h03, b0, b1);
                mmah(acc[4*pp + 1],       h00, h01, h02, h03, b2, b3);
                mmah(acc[NTL + 4*pp],     h10, h11, h12, h13, b0, b1);
                mmah(acc[NTL + 4*pp + 1], h10, h11, h12, h13, b2, b3);
                mmah(acc[4*pp + 2],       h00, h01, h02, h03, c0, c1);
                mmah(acc[4*pp + 3],       h00, h01, h02, h03, c2, c3);
                mmah(acc[NTL + 4*pp + 2], h10, h11, h12, h13, c0, c1);
                mmah(acc[NTL + 4*pp + 3], h10, h11, h12, h13, c2, c3);
                mmah(acc[4*pp],           l00, l01, l02, l03, b0, b1);
                mmah(acc[4*pp + 1],       l00, l01, l02, l03, b2, b3);
                mmah(acc[NTL + 4*pp],     l10, l11, l12, l13, b0, b1);
                mmah(acc[NTL + 4*pp + 1], l10, l11, l12, l13, b2, b3);
                mmah(acc[4*pp + 2],       l00, l01, l02, l03, c0, c1);
                mmah(acc[4*pp + 3],       l00, l01, l02, l03, c2, c3);
                mmah(acc[NTL + 4*pp + 2], l10, l11, l12, l13, c0, c1);
                mmah(acc[NTL + 4*pp + 3], l10, l11, l12, l13, c2, c3);
            }
        } else {
#pragma unroll
            for (int p = 0; p < NTL / 2; ++p) {
                u32 b0, b1, b2, b3;
                ldsm4(wH + bOff + (u32)(p * 16) * ROWB + kt * 32, b0, b1, b2, b3);
                mmah(acc[2*p],           h00, h01, h02, h03, b0, b1);
                mmah(acc[2*p + 1],       h00, h01, h02, h03, b2, b3);
                mmah(acc[NTL + 2*p],     h10, h11, h12, h13, b0, b1);
                mmah(acc[NTL + 2*p + 1], h10, h11, h12, h13, b2, b3);
                mmah(acc[2*p],           l00, l01, l02, l03, b0, b1);
                mmah(acc[2*p + 1],       l00, l01, l02, l03, b2, b3);
                mmah(acc[NTL + 2*p],     l10, l11, l12, l13, b0, b1);
                mmah(acc[NTL + 2*p + 1], l10, l11, l12, l13, b2, b3);
            }
        }
    }
}

// Epilogue: bias + relu, write back as fp16 hi/lo rows.
template<int NTL>
__device__ __forceinline__ void epi_f16(const float (*acc)[4], const float* bias,
                                        char* smc, int lane, int warp) {
    const int r0 = warp * 32 + (lane >> 2);
    const int cb = (lane & 3) * 2;
#pragma unroll
    for (int mt = 0; mt < 2; ++mt) {
#pragma unroll
        for (int nt = 0; nt < NTL; ++nt) {
            const int c = 8 * nt + cb;
            const float b0 = bias[c], b1 = bias[c + 1];
            const float* a = acc[mt * NTL + nt];
            float v0 = fmaxf(a[0] + b0, 0.f), v1 = fmaxf(a[1] + b1, 0.f);
            float v2 = fmaxf(a[2] + b0, 0.f), v3 = fmaxf(a[3] + b1, 0.f);
            const int rA = r0 + 16 * mt, rB = rA + 8;
            u32 h01 = pk2h(v0, v1), h23 = pk2h(v2, v3);
            float2 f01 = up2h(h01), f23 = up2h(h23);
            u32 l01 = pk2h(v0 - f01.x, v1 - f01.y);
            u32 l23 = pk2h(v2 - f23.x, v3 - f23.y);
            *(u32*)(smc + SM_AH + rA * ROWB + c * 2) = h01;
            *(u32*)(smc + SM_AH + rB * ROWB + c * 2) = h23;
            *(u32*)(smc + SM_AL + rA * ROWB + c * 2) = l01;
            *(u32*)(smc + SM_AL + rB * ROWB + c * 2) = l23;
        }
    }
}

// Write one activation row (nch chunks of 8 cols) as fp16 hi/lo.
__device__ __forceinline__ void write_row(char* smc, int s, const float* v, int nch) {
    for (int ch = 0; ch < nch; ++ch) {
        u32 h[4], l[4];
#pragma unroll
        for (int q = 0; q < 4; ++q) {
            float x0 = v[8 * ch + 2 * q], x1 = v[8 * ch + 2 * q + 1];
            u32 hp = pk2h(x0, x1);
            float2 f = up2h(hp);
            h[q] = hp;
            l[q] = pk2h(x0 - f.x, x1 - f.y);
        }
        *(uint4*)(smc + SM_AH + s * ROWB + ch * 16) = make_uint4(h[0], h[1], h[2], h[3]);
        *(uint4*)(smc + SM_AL + s * ROWB + ch * 16) = make_uint4(l[0], l[1], l[2], l[3]);
    }
}

// fp32 W[k][n] (global) -> smem [n][72] fp16, K padded to 64.
__device__ void prep_B(char* smc, const float* W, int Kreal, int Nrows, int stride,
                       int offH) {
    for (int idx = threadIdx.x; idx < Nrows * 64; idx += NT) {
        int nr = idx >> 6, k = idx & 63;
        float x = (k < Kreal) ? __ldg(W + k * stride + nr) : 0.0f;
        u32 p = pk2h(x, x);
        *(unsigned short*)(smc + offH + nr * ROWB + k * 2) = (unsigned short)(p & 0xffffu);
    }
}

// Color-L1 weights with the dir-MLP second layer folded in (R12 ordering):
//   rows 0..14 : cw1 (geo); rows 15..30 : rw2 @ cw1[15:31]; rows 31..62 : cw1 (app)
__device__ void prep_CW1_folded(char* smc, const float* cw1, const float* rw2,
                                int offH) {
    for (int idx = threadIdx.x; idx < 64 * 64; idx += NT) {
        int nr = idx >> 6, k = idx & 63;
        float x;
        if (k < 15) {
            x = __ldg(cw1 + k * 64 + nr);
        } else if (k < 31) {
            const int t = k - 15;
            float s = 0.0f;
#pragma unroll
            for (int j = 0; j < 16; ++j)
                s = fmaf(__ldg(rw2 + t * 16 + j), __ldg(cw1 + (15 + j) * 64 + nr), s);
            x = s;
        } else if (k < 63) {
            x = __ldg(cw1 + k * 64 + nr);
        } else {
            x = 0.0f;
        }
        u32 p = pk2h(x, x);
        *(unsigned short*)(smc + offH + nr * ROWB + k * 2) = (unsigned short)(p & 0xffffu);
    }
}

__device__ void cpyf(char* smc, int off, const float* src, int nf) {
    float* d = (float*)(smc + off);
    for (int t = threadIdx.x; t < nf; t += NT) d[t] = __ldg(src + t);
}

struct ResArr { int r[16]; };

__global__ void __launch_bounds__(NT, 1) nerf_h10_kernel(
    const float* __restrict__ rs, const float* __restrict__ dirs,
    const int*   __restrict__ cam, const float* __restrict__ aabb,
    const float* __restrict__ ht,
    const float* __restrict__ rw1, const float* __restrict__ rb1,
    const float* __restrict__ rw2, const float* __restrict__ rb2,
    const float* __restrict__ dw1, const float* __restrict__ db1,
    const float* __restrict__ dw2, const float* __restrict__ db2,
    const float* __restrict__ dw3, const float* __restrict__ db3,
    const float* __restrict__ cw1, const float* __restrict__ cb1,
    const float* __restrict__ cw2, const float* __restrict__ cb2,
    const float* __restrict__ cw3, const float* __restrict__ cb3,
    const float* __restrict__ app,
    float* __restrict__ out, int n, ResArr RA)
{
    extern __shared__ __align__(128) char smc[];
    u32 sb;
    asm("{ .reg .u64 t; cvta.to.shared.u64 t, %1; cvt.u32.u64 %0, t; }"
        : "=r"(sb) : "l"(smc));

    prep_B(smc, dw1, 32, 64, 64, SM_WD1H);
    prep_B(smc, dw2, 64, 64, 64, SM_WD2H);
    prep_B(smc, dw3, 64, 16, 16, SM_WD3H);
    prep_CW1_folded(smc, cw1, rw2, SM_WC1H);
    prep_B(smc, cw2, 64, 64, 64, SM_WC2H);
    cpyf(smc, SM_DB1, db1, 64);  cpyf(smc, SM_DB2, db2, 64);
    cpyf(smc, SM_DB3, db3, 16);
    // cb1' = cb1 + rb2 @ cw1[15:31]
    if (threadIdx.x < 64) {
        const int t = threadIdx.x;
        float s = __ldg(cb1 + t);
#pragma unroll
        for (int j = 0; j < 16; ++j)
            s = fmaf(__ldg(rb2 + j), __ldg(cw1 + (15 + j) * 64 + t), s);
        ((float*)(smc + SM_CB1))[t] = s;
    }
    cpyf(smc, SM_CB2, cb2, 64);  cpyf(smc, SM_CB3, cb3, 3);
    cpyf(smc, SM_RW1, rw1, 48);  cpyf(smc, SM_RB1, rb1, 16);
    cpyf(smc, SM_CW3, cw3, 192);
    __syncthreads();

    const int tid = threadIdx.x, lane = tid & 31, warp = tid >> 5;
    const u32 AHu = sb + SM_AH, ALu = sb + SM_AL;

    const float a0x = __ldg(aabb + 0), a0y = __ldg(aabb + 1), a0z = __ldg(aabb + 2);
    const float ddx = __ldg(aabb + 3) - a0x;
    const float ddy = __ldg(aabb + 4) - a0y;
    const float ddz = __ldg(aabb + 5) - a0z;
    const float2* htp = (const float2*)ht;
    const float* sDB1 = (const float*)(smc + SM_DB1);
    const float* sDB2 = (const float*)(smc + SM_DB2);
    const float* sDB3 = (const float*)(smc + SM_DB3);
    const float* sCB1 = (const float*)(smc + SM_CB1);
    const float* sCB2 = (const float*)(smc + SM_CB2);
    const float* sCB3 = (const float*)(smc + SM_CB3);
    const float* sRW1 = (const float*)(smc + SM_RW1);
    const float* sRB1 = (const float*)(smc + SM_RB1);
    const float* sCW3 = (const float*)(smc + SM_CW3);
    float* sOUT = (float*)(smc + SM_OUT);

    const int ntiles = (n + TS - 1) / TS;

    for (int tile = blockIdx.x; tile < ntiles; tile += gridDim.x) {
        const int i0 = tile * TS;
        int i = i0 + tid; if (i >= n) i = n - 1;

        // ---- prefetch per-sample scalars early (latency covered by density) ----
        const int   ci  = __ldg(cam + i);
        const float dvx = __ldg(dirs + 3*i + 0);
        const float dvy = __ldg(dirs + 3*i + 1);
        const float dvz = __ldg(dirs + 3*i + 2);

        // ---- hash encode (exact fp32) -> A row (32 cols) ----
        {
            float ev[32];
            const float px = fminf(fmaxf((__ldg(rs + 3*i + 0) - a0x) / ddx, 0.f), 1.f);
            const float py = fminf(fmaxf((__ldg(rs + 3*i + 1) - a0y) / ddy, 0.f), 1.f);
            const float pz = fminf(fmaxf((__ldg(rs + 3*i + 2) - a0z) / ddz, 0.f), 1.f);
#pragma unroll
            for (int l = 0; l < 16; ++l) {
                const int r = RA.r[l];
                const float rf = (float)(r - 1);
                int cx = (int)floorf(px * rf);
                int cy = (int)floorf(py * rf);
                int cz = (int)floorf(pz * rf);
                cx = min(max(cx, 0), r - 1);
                cy = min(max(cy, 0), r - 1);
                cz = min(max(cz, 0), r - 1);
                const unsigned h = ((unsigned)cx + (unsigned)cy * 2481u
                                    + (unsigned)cz * 1941u) & 4095u;
                const float2 f = __ldg(htp + l * 4096 + h);
                ev[2*l] = f.x; ev[2*l + 1] = f.y;
            }
            write_row(smc, tid, ev, 4);
        }
        __syncwarp();

        float acc[16][4];
        // ---- density L1 (K=32) ----
        do_gemm<2, 8>(AHu, ALu, sb + SM_WD1H, lane, warp, acc);
        __syncwarp();
        epi_f16<8>(acc, sDB1, smc, lane, warp);
        __syncwarp();
        // ---- density L2 (K=64) ----
        do_gemm<4, 8>(AHu, ALu, sb + SM_WD2H, lane, warp, acc);
        __syncwarp();
        epi_f16<8>(acc, sDB2, smc, lane, warp);
        __syncwarp();
        // ---- density L3 (64 -> 16) -> sOUT cols 3..18 (raw dfeat) ----
        do_gemm<4, 2>(AHu, ALu, sb + SM_WD3H, lane, warp, acc);
        __syncwarp();
        {
            const int cb = (lane & 3) * 2;
#pragma unroll
            for (int mt = 0; mt < 2; ++mt)
#pragma unroll
                for (int nt = 0; nt < 2; ++nt) {
                    const int c = 8 * nt + cb;
                    const float b0 = sDB3[c], b1 = sDB3[c + 1];
                    const float* a = acc[mt * 2 + nt];
                    const int rA = warp * 32 + 16 * mt + (lane >> 2), rB = rA + 8;
                    sOUT[rA * 19 + 3 + c] = a[0] + b0;
                    sOUT[rA * 19 + 4 + c] = a[1] + b1;
                    sOUT[rB * 19 + 3 + c] = a[2] + b0;
                    sOUT[rB * 19 + 4 + c] = a[3] + b1;
                }
        }
        __syncwarp();

        // ---- cin build: issue app LDGs FIRST (exposure covered by dir MLP) ----
        float df0;
        {
            // 8 independent LDG.128 issued up-front
            float4 ap[8];
            const float4* a4 = (const float4*)(app + (size_t)ci * 32);
#pragma unroll
            for (int q = 0; q < 8; ++q) ap[q] = __ldg(a4 + q);

            // cover: dfeat read + dir layer-1 (rw2 folded into cw1)
            const float* drow = sOUT + (warp * 32 + lane) * 19 + 3;
            float cin[64];
            df0 = drow[0];
#pragma unroll
            for (int j = 0; j < 15; ++j) cin[j] = drow[1 + j];
            const float dv[3] = { dvx, dvy, dvz };
#pragma unroll
            for (int j = 0; j < 16; ++j) {
                float a = sRB1[j];
#pragma unroll
                for (int k = 0; k < 3; ++k)
                    a = fmaf(dv[k], sRW1[k*16 + j], a);
                cin[15 + j] = fmaxf(a, 0.0f);
            }
            // consume app last
#pragma unroll
            for (int q = 0; q < 8; ++q) {
                cin[31 + 4*q + 0] = ap[q].x; cin[31 + 4*q + 1] = ap[q].y;
                cin[31 + 4*q + 2] = ap[q].z; cin[31 + 4*q + 3] = ap[q].w;
            }
            cin[63] = 0.0f;
            write_row(smc, tid, cin, 8);
        }
        __syncwarp();
        // ---- color L1 (K=64, folded weights, cb1') ----
        do_gemm<4, 8>(AHu, ALu, sb + SM_WC1H, lane, warp, acc);
        __syncwarp();
        epi_f16<8>(acc, sCB1, smc, lane, warp);
        __syncwarp();
        // ---- color L2 (K=64); final 64->3 straight from accumulators ----
        do_gemm<4, 8>(AHu, ALu, sb + SM_WC2H, lane, warp, acc);
        __syncwarp();
        {
            const int cb = (lane & 3) * 2;
#pragma unroll
            for (int mt = 0; mt < 2; ++mt)
#pragma unroll
                for (int nt = 0; nt < 8; ++nt) {
                    const int c = 8 * nt + cb;
                    float* a = acc[mt * 8 + nt];
                    a[0] = fmaxf(a[0] + sCB2[c], 0.f);
                    a[1] = fmaxf(a[1] + sCB2[c + 1], 0.f);
                    a[2] = fmaxf(a[2] + sCB2[c], 0.f);
                    a[3] = fmaxf(a[3] + sCB2[c + 1], 0.f);
                }
            float w3[8][2][3];
#pragma unroll
            for (int nt = 0; nt < 8; ++nt)
#pragma unroll
                for (int e = 0; e < 2; ++e) {
                    const int c = 8 * nt + cb + e;
#pragma unroll
                    for (int j = 0; j < 3; ++j) w3[nt][e][j] = sCW3[c * 3 + j];
                }
            float s[4][3];
#pragma unroll
            for (int v = 0; v < 4; ++v)
#pragma unroll
                for (int j = 0; j < 3; ++j) s[v][j] = 0.f;
#pragma unroll
            for (int mt = 0; mt < 2; ++mt)
#pragma unroll
                for (int h = 0; h < 2; ++h)
#pragma unroll
                    for (int nt = 0; nt < 8; ++nt)
#pragma unroll
                        for (int e = 0; e < 2; ++e) {
                            const float x = acc[mt * 8 + nt][2 * h + e];
#pragma unroll
                            for (int j = 0; j < 3; ++j)
                                s[mt * 2 + h][j] = fmaf(x, w3[nt][e][j],
                                                        s[mt * 2 + h][j]);
                        }
#pragma unroll
            for (int v = 0; v < 4; ++v)
#pragma unroll
                for (int j = 0; j < 3; ++j) {
                    s[v][j] += __shfl_xor_sync(0xffffffffu, s[v][j], 1);
                    s[v][j] += __shfl_xor_sync(0xffffffffu, s[v][j], 2);
                }
            const int q = lane & 3;
            const int row = warp * 32 + 16 * (q >> 1) + 8 * (q & 1) + (lane >> 2);
            const float r0 = s[q][0], r1 = s[q][1], r2 = s[q][2];
            sOUT[row * 19 + 0] = 1.0f / (1.0f + expf(-(r0 + sCB3[0])));
            sOUT[row * 19 + 1] = 1.0f / (1.0f + expf(-(r1 + sCB3[1])));
            sOUT[row * 19 + 2] = 1.0f / (1.0f + expf(-(r2 + sCB3[2])));
            sOUT[(warp * 32 + lane) * 19 + 3] = fmaxf(df0, 0.0f);
        }
        __syncwarp();
        // ---- linear coalesced store: staging layout == output layout ----
        {
            const int m = min(TS, n - i0);
            const int vw = min(32, m - warp * 32);
            if (vw > 0) {
                float* gbase = out + (size_t)(i0 + warp * 32) * 19;
                const float* sbase = sOUT + (warp * 32) * 19;
                if (vw == 32) {
                    const float4* s4 = (const float4*)sbase;
                    float4* g4 = (float4*)gbase;
#pragma unroll
                    for (int j = 0; j < 5; ++j) {
                        int idx = lane + j * 32;
                        if (idx < 152) g4[idx] = s4[idx];
                    }
                } else {
                    for (int j = lane; j < vw * 19; j += 32) gbase[j] = sbase[j];
                }
            }
        }
        __syncwarp();
    }
}

extern "C" void kernel_launch(void* const* d_in, const int* in_sizes, int n_in,
                              void* d_out, int out_size) {
    const float* rs   = (const float*)d_in[0];
    const float* dirs = (const float*)d_in[1];
    const int*   cam  = (const int*)d_in[2];
    const float* aabb = (const float*)d_in[3];
    const float* ht   = (const float*)d_in[4];
    const float* rw1  = (const float*)d_in[5];
    const float* rb1  = (const float*)d_in[6];
    const float* rw2  = (const float*)d_in[7];
    const float* rb2  = (const float*)d_in[8];
    const float* dw1  = (const float*)d_in[9];
    const float* db1  = (const float*)d_in[10];
    const float* dw2  = (const float*)d_in[11];
    const float* db2  = (const float*)d_in[12];
    const float* dw3  = (const float*)d_in[13];
    const float* db3  = (const float*)d_in[14];
    const float* cw1  = (const float*)d_in[15];
    const float* cb1  = (const float*)d_in[16];
    const float* cw2  = (const float*)d_in[17];
    const float* cb2  = (const float*)d_in[18];
    const float* cw3  = (const float*)d_in[19];
    const float* cb3  = (const float*)d_in[20];
    const float* app  = (const float*)d_in[21];
    float* out = (float*)d_out;

    const int n = in_sizes[0] / 3;

    ResArr ra;
    double growth = exp((log(2048.0) - log(16.0)) / 15.0);
    for (int i = 0; i < 16; ++i)
        ra.r[i] = (int)(16.0 * pow(growth, (double)i));

    cudaFuncSetAttribute(nerf_h10_kernel,
                         cudaFuncAttributeMaxDynamicSharedMemorySize, SMEM_BYTES);

    dim3 grid(148), block(NT);   // 1 CTA/SM persistent, 12 warps, warp-independent
    nerf_h10_kernel<<<grid, block, SMEM_BYTES>>>(
        rs, dirs, cam, aabb, ht,
        rw1, rb1, rw2, rb2,
        dw1, db1, dw2, db2, dw3, db3,
        cw1, cb1, cw2, cb2, cw3, cb3,
        app, out, n, ra);
}

// round 16
// speedup vs baseline: 1.2651x; 1.1928x over previous
#include <cuda_runtime.h>
#include <cuda_fp16.h>
#include <cstdint>
#include <cmath>

typedef unsigned int u32;

#define NT 384
#define TS 384
#define ROWB 144          // bytes per activation/weight row (72 fp16)

// ---- smem byte offsets ----
// NOTE: SM_CW3 spans [41616, 42384). SM_AH MUST start >= 42384 (R9 bug).
#define SM_WD1H 0
#define SM_WD2H 9216
#define SM_WD3H 18432
#define SM_WC1H 20736
#define SM_WC2H 29952
#define SM_DB1  39168
#define SM_DB2  39424
#define SM_DB3  39680
#define SM_CB1  39744
#define SM_CB2  40000
#define SM_CB3  40256
#define SM_RW1  40272
#define SM_RB1  40464
#define SM_CW3  41616     // ends 42384
#define SM_AH   42496     // 384 rows x 144B fp16 (hi)   [42496..97792)
#define SM_AL   97792     // 384 rows x 144B fp16 (lo)   [97792..153088)
#define SM_OUT  153088    // 384 rows x 19 fp32 staging  [153088..182272)
#define SMEM_BYTES 182272

__device__ __forceinline__ u32 pk2h(float vlo, float vhi) {
    u32 r; asm("cvt.rn.f16x2.f32 %0, %1, %2;" : "=r"(r) : "f"(vhi), "f"(vlo));
    return r;
}
__device__ __forceinline__ float2 up2h(u32 p) {
    float lo, hi;
    asm("{ .reg .f16 l, h; mov.b32 {l, h}, %2; cvt.f32.f16 %0, l; cvt.f32.f16 %1, h; }"
        : "=f"(lo), "=f"(hi) : "r"(p));
    return make_float2(lo, hi);
}
__device__ __forceinline__ void ldsm4(u32 addr, u32& r0, u32& r1, u32& r2, u32& r3) {
    asm volatile("ldmatrix.sync.aligned.m8n8.x4.shared.b16 {%0,%1,%2,%3}, [%4];"
                 : "=r"(r0), "=r"(r1), "=r"(r2), "=r"(r3) : "r"(addr) : "memory");
}
__device__ __forceinline__ void mmah(float* c, u32 a0, u32 a1, u32 a2, u32 a3,
                                     u32 b0, u32 b1) {
    asm("mma.sync.aligned.m16n8k16.row.col.f32.f16.f16.f32 "
        "{%0,%1,%2,%3},{%4,%5,%6,%7},{%8,%9},{%0,%1,%2,%3};"
        : "+f"(c[0]), "+f"(c[1]), "+f"(c[2]), "+f"(c[3])
        : "r"(a0), "r"(a1), "r"(a2), "r"(a3), "r"(b0), "r"(b1));
}

// GEMM: acc[2*NTL][4] += ( A[warp rows] * W^T ).  All smem.
// SPLIT=true : fp16 2-term A (hi + lo), bit-exact fp32-ish path (density chain)
// SPLIT=false: single-fp16 A (color chain; rgb-only influence, error ~1e-5)
template<int KT, int NTL, bool SPLIT>
__device__ __forceinline__ void do_gemm(u32 aH, u32 aL, u32 wH,
                                        int lane, int warp, float (*acc)[4]) {
#pragma unroll
    for (int t = 0; t < 2 * NTL; ++t) {
        acc[t][0] = 0.f; acc[t][1] = 0.f; acc[t][2] = 0.f; acc[t][3] = 0.f;
    }
    const u32 aOff = (u32)(warp * 32 + (lane & 15)) * ROWB + (u32)(lane >> 4) * 16;
    const u32 bOff = (u32)((lane & 7) + ((lane >> 4) & 1) * 8) * ROWB
                   + (u32)((lane >> 3) & 1) * 16;
#pragma unroll
    for (int kt = 0; kt < KT; ++kt) {
        u32 h00,h01,h02,h03, h10,h11,h12,h13;
        u32 l00,l01,l02,l03, l10,l11,l12,l13;
        ldsm4(aH + aOff + kt * 32,             h00, h01, h02, h03);
        ldsm4(aH + aOff + 16 * ROWB + kt * 32, h10, h11, h12, h13);
        if (SPLIT) {
            ldsm4(aL + aOff + kt * 32,             l00, l01, l02, l03);
            ldsm4(aL + aOff + 16 * ROWB + kt * 32, l10, l11, l12, l13);
        }
        if constexpr (NTL >= 4) {
#pragma unroll
            for (int pp = 0; pp < NTL / 4; ++pp) {
                u32 b0, b1, b2, b3, c0, c1, c2, c3;
                ldsm4(wH + bOff + (u32)((2*pp)   * 16) * ROWB + kt * 32, b0, b1, b2, b3);
                ldsm4(wH + bOff + (u32)((2*pp+1) * 16) * ROWB + kt * 32, c0, c1, c2, c3);
                mmah(acc[4*pp],           h00, h01, h02, h03, b0, b1);
                mmah(acc[4*pp + 1],       h00, h01, h02, h03, b2, b3);
                mmah(acc[NTL + 4*pp],     h10, h11, h12, h13, b0, b1);
                mmah(acc[NTL + 4*pp + 1], h10, h11, h12, h13, b2, b3);
                mmah(acc[4*pp + 2],       h00, h01, h02, h03, c0, c1);
                mmah(acc[4*pp + 3],       h00, h01, h02, h03, c2, c3);
                mmah(acc[NTL + 4*pp + 2], h10, h11, h12, h13, c0, c1);
                mmah(acc[NTL + 4*pp + 3], h10, h11, h12, h13, c2, c3);
                if (SPLIT) {
                    mmah(acc[4*pp],           l00, l01, l02, l03, b0, b1);
                    mmah(acc[4*pp + 1],       l00, l01, l02, l03, b2, b3);
                    mmah(acc[NTL + 4*pp],     l10, l11, l12, l13, b0, b1);
                    mmah(acc[NTL + 4*pp + 1], l10, l11, l12, l13, b2, b3);
                    mmah(acc[4*pp + 2],       l00, l01, l02, l03, c0, c1);
                    mmah(acc[4*pp + 3],       l00, l01, l02, l03, c2, c3);
                    mmah(acc[NTL + 4*pp + 2], l10, l11, l12, l13, c0, c1);
                    mmah(acc[NTL + 4*pp + 3], l10, l11, l12, l13, c2, c3);
                }
            }
        } else {
#pragma unroll
            for (int p = 0; p < NTL / 2; ++p) {
                u32 b0, b1, b2, b3;
                ldsm4(wH + bOff + (u32)(p * 16) * ROWB + kt * 32, b0, b1, b2, b3);
                mmah(acc[2*p],           h00, h01, h02, h03, b0, b1);
                mmah(acc[2*p + 1],       h00, h01, h02, h03, b2, b3);
                mmah(acc[NTL + 2*p],     h10, h11, h12, h13, b0, b1);
                mmah(acc[NTL + 2*p + 1], h10, h11, h12, h13, b2, b3);
                if (SPLIT) {
                    mmah(acc[2*p],           l00, l01, l02, l03, b0, b1);
                    mmah(acc[2*p + 1],       l00, l01, l02, l03, b2, b3);
                    mmah(acc[NTL + 2*p],     l10, l11, l12, l13, b0, b1);
                    mmah(acc[NTL + 2*p + 1], l10, l11, l12, l13, b2, b3);
                }
            }
        }
    }
}

// Epilogue: bias + relu, write back as fp16 rows (hi, and lo when WLO).
template<int NTL, bool WLO>
__device__ __forceinline__ void epi_f16(const float (*acc)[4], const float* bias,
                                        char* smc, int lane, int warp) {
    const int r0 = warp * 32 + (lane >> 2);
    const int cb = (lane & 3) * 2;
#pragma unroll
    for (int mt = 0; mt < 2; ++mt) {
#pragma unroll
        for (int nt = 0; nt < NTL; ++nt) {
            const int c = 8 * nt + cb;
            const float b0 = bias[c], b1 = bias[c + 1];
            const float* a = acc[mt * NTL + nt];
            float v0 = fmaxf(a[0] + b0, 0.f), v1 = fmaxf(a[1] + b1, 0.f);
            float v2 = fmaxf(a[2] + b0, 0.f), v3 = fmaxf(a[3] + b1, 0.f);
            const int rA = r0 + 16 * mt, rB = rA + 8;
            u32 h01 = pk2h(v0, v1), h23 = pk2h(v2, v3);
            *(u32*)(smc + SM_AH + rA * ROWB + c * 2) = h01;
            *(u32*)(smc + SM_AH + rB * ROWB + c * 2) = h23;
            if (WLO) {
                float2 f01 = up2h(h01), f23 = up2h(h23);
                u32 l01 = pk2h(v0 - f01.x, v1 - f01.y);
                u32 l23 = pk2h(v2 - f23.x, v3 - f23.y);
                *(u32*)(smc + SM_AL + rA * ROWB + c * 2) = l01;
                *(u32*)(smc + SM_AL + rB * ROWB + c * 2) = l23;
            }
        }
    }
}

// Write one activation row (nch chunks of 8 cols) as fp16; lo plane when WLO.
template<bool WLO>
__device__ __forceinline__ void write_row(char* smc, int s, const float* v, int nch) {
    for (int ch = 0; ch < nch; ++ch) {
        u32 h[4], l[4];
#pragma unroll
        for (int q = 0; q < 4; ++q) {
            float x0 = v[8 * ch + 2 * q], x1 = v[8 * ch + 2 * q + 1];
            u32 hp = pk2h(x0, x1);
            h[q] = hp;
            if (WLO) {
                float2 f = up2h(hp);
                l[q] = pk2h(x0 - f.x, x1 - f.y);
            }
        }
        *(uint4*)(smc + SM_AH + s * ROWB + ch * 16) = make_uint4(h[0], h[1], h[2], h[3]);
        if (WLO)
            *(uint4*)(smc + SM_AL + s * ROWB + ch * 16) = make_uint4(l[0], l[1], l[2], l[3]);
    }
}

// fp32 W[k][n] (global) -> smem [n][72] fp16, K padded to 64.
__device__ void prep_B(char* smc, const float* W, int Kreal, int Nrows, int stride,
                       int offH) {
    for (int idx = threadIdx.x; idx < Nrows * 64; idx += NT) {
        int nr = idx >> 6, k = idx & 63;
        float x = (k < Kreal) ? __ldg(W + k * stride + nr) : 0.0f;
        u32 p = pk2h(x, x);
        *(unsigned short*)(smc + offH + nr * ROWB + k * 2) = (unsigned short)(p & 0xffffu);
    }
}

// Color-L1 weights with the dir-MLP second layer folded in (R12 ordering):
//   rows 0..14 : cw1 (geo); rows 15..30 : rw2 @ cw1[15:31]; rows 31..62 : cw1 (app)
__device__ void prep_CW1_folded(char* smc, const float* cw1, const float* rw2,
                                int offH) {
    for (int idx = threadIdx.x; idx < 64 * 64; idx += NT) {
        int nr = idx >> 6, k = idx & 63;
        float x;
        if (k < 15) {
            x = __ldg(cw1 + k * 64 + nr);
        } else if (k < 31) {
            const int t = k - 15;
            float s = 0.0f;
#pragma unroll
            for (int j = 0; j < 16; ++j)
                s = fmaf(__ldg(rw2 + t * 16 + j), __ldg(cw1 + (15 + j) * 64 + nr), s);
            x = s;
        } else if (k < 63) {
            x = __ldg(cw1 + k * 64 + nr);
        } else {
            x = 0.0f;
        }
        u32 p = pk2h(x, x);
        *(unsigned short*)(smc + offH + nr * ROWB + k * 2) = (unsigned short)(p & 0xffffu);
    }
}

__device__ void cpyf(char* smc, int off, const float* src, int nf) {
    float* d = (float*)(smc + off);
    for (int t = threadIdx.x; t < nf; t += NT) d[t] = __ldg(src + t);
}

struct ResArr { int r[16]; };

__global__ void __launch_bounds__(NT, 1) nerf_h11_kernel(
    const float* __restrict__ rs, const float* __restrict__ dirs,
    const int*   __restrict__ cam, const float* __restrict__ aabb,
    const float* __restrict__ ht,
    const float* __restrict__ rw1, const float* __restrict__ rb1,
    const float* __restrict__ rw2, const float* __restrict__ rb2,
    const float* __restrict__ dw1, const float* __restrict__ db1,
    const float* __restrict__ dw2, const float* __restrict__ db2,
    const float* __restrict__ dw3, const float* __restrict__ db3,
    const float* __restrict__ cw1, const float* __restrict__ cb1,
    const float* __restrict__ cw2, const float* __restrict__ cb2,
    const float* __restrict__ cw3, const float* __restrict__ cb3,
    const float* __restrict__ app,
    float* __restrict__ out, int n, ResArr RA)
{
    extern __shared__ __align__(128) char smc[];
    u32 sb;
    asm("{ .reg .u64 t; cvta.to.shared.u64 t, %1; cvt.u32.u64 %0, t; }"
        : "=r"(sb) : "l"(smc));

    prep_B(smc, dw1, 32, 64, 64, SM_WD1H);
    prep_B(smc, dw2, 64, 64, 64, SM_WD2H);
    prep_B(smc, dw3, 64, 16, 16, SM_WD3H);
    prep_CW1_folded(smc, cw1, rw2, SM_WC1H);
    prep_B(smc, cw2, 64, 64, 64, SM_WC2H);
    cpyf(smc, SM_DB1, db1, 64);  cpyf(smc, SM_DB2, db2, 64);
    cpyf(smc, SM_DB3, db3, 16);
    // cb1' = cb1 + rb2 @ cw1[15:31]
    if (threadIdx.x < 64) {
        const int t = threadIdx.x;
        float s = __ldg(cb1 + t);
#pragma unroll
        for (int j = 0; j < 16; ++j)
            s = fmaf(__ldg(rb2 + j), __ldg(cw1 + (15 + j) * 64 + t), s);
        ((float*)(smc + SM_CB1))[t] = s;
    }
    cpyf(smc, SM_CB2, cb2, 64);  cpyf(smc, SM_CB3, cb3, 3);
    cpyf(smc, SM_RW1, rw1, 48);  cpyf(smc, SM_RB1, rb1, 16);
    cpyf(smc, SM_CW3, cw3, 192);
    __syncthreads();

    const int tid = threadIdx.x, lane = tid & 31, warp = tid >> 5;
    const u32 AHu = sb + SM_AH, ALu = sb + SM_AL;

    const float a0x = __ldg(aabb + 0), a0y = __ldg(aabb + 1), a0z = __ldg(aabb + 2);
    const float ddx = __ldg(aabb + 3) - a0x;
    const float ddy = __ldg(aabb + 4) - a0y;
    const float ddz = __ldg(aabb + 5) - a0z;
    const float2* htp = (const float2*)ht;
    const float* sDB1 = (const float*)(smc + SM_DB1);
    const float* sDB2 = (const float*)(smc + SM_DB2);
    const float* sDB3 = (const float*)(smc + SM_DB3);
    const float* sCB1 = (const float*)(smc + SM_CB1);
    const float* sCB2 = (const float*)(smc + SM_CB2);
    const float* sCB3 = (const float*)(smc + SM_CB3);
    const float* sRW1 = (const float*)(smc + SM_RW1);
    const float* sRB1 = (const float*)(smc + SM_RB1);
    const float* sCW3 = (const float*)(smc + SM_CW3);
    float* sOUT = (float*)(smc + SM_OUT);

    const int ntiles = (n + TS - 1) / TS;

    for (int tile = blockIdx.x; tile < ntiles; tile += gridDim.x) {
        const int i0 = tile * TS;
        int i = i0 + tid; if (i >= n) i = n - 1;

        const int   ci  = __ldg(cam + i);
        const float dvx = __ldg(dirs + 3*i + 0);
        const float dvy = __ldg(dirs + 3*i + 1);
        const float dvz = __ldg(dirs + 3*i + 2);

        // ---- hash encode (exact fp32) -> A row (32 cols, hi+lo) ----
        {
            float ev[32];
            const float px = fminf(fmaxf((__ldg(rs + 3*i + 0) - a0x) / ddx, 0.f), 1.f);
            const float py = fminf(fmaxf((__ldg(rs + 3*i + 1) - a0y) / ddy, 0.f), 1.f);
            const float pz = fminf(fmaxf((__ldg(rs + 3*i + 2) - a0z) / ddz, 0.f), 1.f);
#pragma unroll
            for (int l = 0; l < 16; ++l) {
                const int r = RA.r[l];
                const float rf = (float)(r - 1);
                int cx = (int)floorf(px * rf);
                int cy = (int)floorf(py * rf);
                int cz = (int)floorf(pz * rf);
                cx = min(max(cx, 0), r - 1);
                cy = min(max(cy, 0), r - 1);
                cz = min(max(cz, 0), r - 1);
                const unsigned h = ((unsigned)cx + (unsigned)cy * 2481u
                                    + (unsigned)cz * 1941u) & 4095u;
                const float2 f = __ldg(htp + l * 4096 + h);
                ev[2*l] = f.x; ev[2*l + 1] = f.y;
            }
            write_row<true>(smc, tid, ev, 4);
        }
        __syncwarp();

        float acc[16][4];
        // ---- density chain: full 2-term split (geo/density exported raw) ----
        do_gemm<2, 8, true>(AHu, ALu, sb + SM_WD1H, lane, warp, acc);
        __syncwarp();
        epi_f16<8, true>(acc, sDB1, smc, lane, warp);
        __syncwarp();
        do_gemm<4, 8, true>(AHu, ALu, sb + SM_WD2H, lane, warp, acc);
        __syncwarp();
        epi_f16<8, true>(acc, sDB2, smc, lane, warp);
        __syncwarp();
        do_gemm<4, 2, true>(AHu, ALu, sb + SM_WD3H, lane, warp, acc);
        __syncwarp();
        {
            const int cb = (lane & 3) * 2;
#pragma unroll
            for (int mt = 0; mt < 2; ++mt)
#pragma unroll
                for (int nt = 0; nt < 2; ++nt) {
                    const int c = 8 * nt + cb;
                    const float b0 = sDB3[c], b1 = sDB3[c + 1];
                    const float* a = acc[mt * 2 + nt];
                    const int rA = warp * 32 + 16 * mt + (lane >> 2), rB = rA + 8;
                    sOUT[rA * 19 + 3 + c] = a[0] + b0;
                    sOUT[rA * 19 + 4 + c] = a[1] + b1;
                    sOUT[rB * 19 + 3 + c] = a[2] + b0;
                    sOUT[rB * 19 + 4 + c] = a[3] + b1;
                }
        }
        __syncwarp();

        // ---- cin build (hi plane only; color chain is single-fp16) ----
        float df0;
        {
            float4 ap[8];
            const float4* a4 = (const float4*)(app + (size_t)ci * 32);
#pragma unroll
            for (int q = 0; q < 8; ++q) ap[q] = __ldg(a4 + q);

            const float* drow = sOUT + (warp * 32 + lane) * 19 + 3;
            float cin[64];
            df0 = drow[0];
#pragma unroll
            for (int j = 0; j < 15; ++j) cin[j] = drow[1 + j];
            const float dv[3] = { dvx, dvy, dvz };
#pragma unroll
            for (int j = 0; j < 16; ++j) {
                float a = sRB1[j];
#pragma unroll
                for (int k = 0; k < 3; ++k)
                    a = fmaf(dv[k], sRW1[k*16 + j], a);
                cin[15 + j] = fmaxf(a, 0.0f);
            }
#pragma unroll
            for (int q = 0; q < 8; ++q) {
                cin[31 + 4*q + 0] = ap[q].x; cin[31 + 4*q + 1] = ap[q].y;
                cin[31 + 4*q + 2] = ap[q].z; cin[31 + 4*q + 3] = ap[q].w;
            }
            cin[63] = 0.0f;
            write_row<false>(smc, tid, cin, 8);
        }
        __syncwarp();
        // ---- color L1 (single-fp16 A, folded weights, cb1') ----
        do_gemm<4, 8, false>(AHu, ALu, sb + SM_WC1H, lane, warp, acc);
        __syncwarp();
        epi_f16<8, false>(acc, sCB1, smc, lane, warp);
        __syncwarp();
        // ---- color L2 (single-fp16 A); final 64->3 from accumulators ----
        do_gemm<4, 8, false>(AHu, ALu, sb + SM_WC2H, lane, warp, acc);
        __syncwarp();
        {
            const int cb = (lane & 3) * 2;
#pragma unroll
            for (int mt = 0; mt < 2; ++mt)
#pragma unroll
                for (int nt = 0; nt < 8; ++nt) {
                    const int c = 8 * nt + cb;
                    float* a = acc[mt * 8 + nt];
                    a[0] = fmaxf(a[0] + sCB2[c], 0.f);
                    a[1] = fmaxf(a[1] + sCB2[c + 1], 0.f);
                    a[2] = fmaxf(a[2] + sCB2[c], 0.f);
                    a[3] = fmaxf(a[3] + sCB2[c + 1], 0.f);
                }
            float w3[8][2][3];
#pragma unroll
            for (int nt = 0; nt < 8; ++nt)
#pragma unroll
                for (int e = 0; e < 2; ++e) {
                    const int c = 8 * nt + cb + e;
#pragma unroll
                    for (int j = 0; j < 3; ++j) w3[nt][e][j] = sCW3[c * 3 + j];
                }
            float s[4][3];
#pragma unroll
            for (int v = 0; v < 4; ++v)
#pragma unroll
                for (int j = 0; j < 3; ++j) s[v][j] = 0.f;
#pragma unroll
            for (int mt = 0; mt < 2; ++mt)
#pragma unroll
                for (int h = 0; h < 2; ++h)
#pragma unroll
                    for (int nt = 0; nt < 8; ++nt)
#pragma unroll
                        for (int e = 0; e < 2; ++e) {
                            const float x = acc[mt * 8 + nt][2 * h + e];
#pragma unroll
                            for (int j = 0; j < 3; ++j)
                                s[mt * 2 + h][j] = fmaf(x, w3[nt][e][j],
                                                        s[mt * 2 + h][j]);
                        }
#pragma unroll
            for (int v = 0; v < 4; ++v)
#pragma unroll
                for (int j = 0; j < 3; ++j) {
                    s[v][j] += __shfl_xor_sync(0xffffffffu, s[v][j], 1);
                    s[v][j] += __shfl_xor_sync(0xffffffffu, s[v][j], 2);
                }
            const int q = lane & 3;
            const int row = warp * 32 + 16 * (q >> 1) + 8 * (q & 1) + (lane >> 2);
            const float r0 = s[q][0], r1 = s[q][1], r2 = s[q][2];
            sOUT[row * 19 + 0] = 1.0f / (1.0f + expf(-(r0 + sCB3[0])));
            sOUT[row * 19 + 1] = 1.0f / (1.0f + expf(-(r1 + sCB3[1])));
            sOUT[row * 19 + 2] = 1.0f / (1.0f + expf(-(r2 + sCB3[2])));
            sOUT[(warp * 32 + lane) * 19 + 3] = fmaxf(df0, 0.0f);
        }
        __syncwarp();
        // ---- linear coalesced store ----
        {
            const int m = min(TS, n - i0);
            const int vw = min(32, m - warp * 32);
            if (vw > 0) {
                float* gbase = out + (size_t)(i0 + warp * 32) * 19;
                const float* sbase = sOUT + (warp * 32) * 19;
                if (vw == 32) {
                    const float4* s4 = (const float4*)sbase;
                    float4* g4 = (float4*)gbase;
#pragma unroll
                    for (int j = 0; j < 5; ++j) {
                        int idx = lane + j * 32;
                        if (idx < 152) g4[idx] = s4[idx];
                    }
                } else {
                    for (int j = lane; j < vw * 19; j += 32) gbase[j] = sbase[j];
                }
            }
        }
        __syncwarp();
    }
}

extern "C" void kernel_launch(void* const* d_in, const int* in_sizes, int n_in,
                              void* d_out, int out_size) {
    const float* rs   = (const float*)d_in[0];
    const float* dirs = (const float*)d_in[1];
    const int*   cam  = (const int*)d_in[2];
    const float* aabb = (const float*)d_in[3];
    const float* ht   = (const float*)d_in[4];
    const float* rw1  = (const float*)d_in[5];
    const float* rb1  = (const float*)d_in[6];
    const float* rw2  = (const float*)d_in[7];
    const float* rb2  = (const float*)d_in[8];
    const float* dw1  = (const float*)d_in[9];
    const float* db1  = (const float*)d_in[10];
    const float* dw2  = (const float*)d_in[11];
    const float* db2  = (const float*)d_in[12];
    const float* dw3  = (const float*)d_in[13];
    const float* db3  = (const float*)d_in[14];
    const float* cw1  = (const float*)d_in[15];
    const float* cb1  = (const float*)d_in[16];
    const float* cw2  = (const float*)d_in[17];
    const float* cb2  = (const float*)d_in[18];
    const float* cw3  = (const float*)d_in[19];
    const float* cb3  = (const float*)d_in[20];
    const float* app  = (const float*)d_in[21];
    float* out = (float*)d_out;

    const int n = in_sizes[0] / 3;

    ResArr ra;
    double growth = exp((log(2048.0) - log(16.0)) / 15.0);
    for (int i = 0; i < 16; ++i)
        ra.r[i] = (int)(16.0 * pow(growth, (double)i));

    cudaFuncSetAttribute(nerf_h11_kernel,
                         cudaFuncAttributeMaxDynamicSharedMemorySize, SMEM_BYTES);

    dim3 grid(148), block(NT);   // 1 CTA/SM persistent, 12 warps, warp-independent
    nerf_h11_kernel<<<grid, block, SMEM_BYTES>>>(
        rs, dirs, cam, aabb, ht,
        rw1, rb1, rw2, rb2,
        dw1, db1, dw2, db2, dw3, db3,
        cw1, cb1, cw2, cb2, cw3, cb3,
        app, out, n, ra);
}

// round 17
// speedup vs baseline: 1.5828x; 1.2512x over previous
#include <cuda_runtime.h>
#include <cuda_fp16.h>
#include <cstdint>
#include <cmath>

typedef unsigned int u32;

#define NT 384
#define TS 384
#define ROWB 144          // bytes per activation/weight row (72 fp16)

// ---- smem byte offsets ----
// NOTE: SM_CW3 spans [41616, 42384). SM_AH MUST start >= 42384 (R9 bug).
#define SM_WD1H 0
#define SM_WD2H 9216
#define SM_WD3H 18432
#define SM_WC1H 20736
#define SM_WC2H 29952
#define SM_DB1  39168
#define SM_DB2  39424
#define SM_DB3  39680
#define SM_CB1  39744
#define SM_CB2  40000
#define SM_CB3  40256
#define SM_RW1  40272
#define SM_RB1  40464
#define SM_CW3  41616     // ends 42384
#define SM_AH   42496     // 384 rows x 144B fp16        [42496..97792)
#define SM_OUT  97792     // 384 rows x 19 fp32 staging  [97792..126976)
#define SMEM_BYTES 126976

__device__ __forceinline__ u32 pk2h(float vlo, float vhi) {
    u32 r; asm("cvt.rn.f16x2.f32 %0, %1, %2;" : "=r"(r) : "f"(vhi), "f"(vlo));
    return r;
}
__device__ __forceinline__ void ldsm4(u32 addr, u32& r0, u32& r1, u32& r2, u32& r3) {
    asm volatile("ldmatrix.sync.aligned.m8n8.x4.shared.b16 {%0,%1,%2,%3}, [%4];"
                 : "=r"(r0), "=r"(r1), "=r"(r2), "=r"(r3) : "r"(addr) : "memory");
}
__device__ __forceinline__ void mmah(float* c, u32 a0, u32 a1, u32 a2, u32 a3,
                                     u32 b0, u32 b1) {
    asm("mma.sync.aligned.m16n8k16.row.col.f32.f16.f16.f32 "
        "{%0,%1,%2,%3},{%4,%5,%6,%7},{%8,%9},{%0,%1,%2,%3};"
        : "+f"(c[0]), "+f"(c[1]), "+f"(c[2]), "+f"(c[3])
        : "r"(a0), "r"(a1), "r"(a2), "r"(a3), "r"(b0), "r"(b1));
}

// GEMM: acc[2*NTL][4] += single-fp16( A[warp rows] * W^T ).  All smem.
template<int KT, int NTL>
__device__ __forceinline__ void do_gemm(u32 aH, u32 wH,
                                        int lane, int warp, float (*acc)[4]) {
#pragma unroll
    for (int t = 0; t < 2 * NTL; ++t) {
        acc[t][0] = 0.f; acc[t][1] = 0.f; acc[t][2] = 0.f; acc[t][3] = 0.f;
    }
    const u32 aOff = (u32)(warp * 32 + (lane & 15)) * ROWB + (u32)(lane >> 4) * 16;
    const u32 bOff = (u32)((lane & 7) + ((lane >> 4) & 1) * 8) * ROWB
                   + (u32)((lane >> 3) & 1) * 16;
#pragma unroll
    for (int kt = 0; kt < KT; ++kt) {
        u32 h00,h01,h02,h03, h10,h11,h12,h13;
        ldsm4(aH + aOff + kt * 32,             h00, h01, h02, h03);
        ldsm4(aH + aOff + 16 * ROWB + kt * 32, h10, h11, h12, h13);
        if constexpr (NTL >= 4) {
#pragma unroll
            for (int pp = 0; pp < NTL / 4; ++pp) {
                u32 b0, b1, b2, b3, c0, c1, c2, c3;
                ldsm4(wH + bOff + (u32)((2*pp)   * 16) * ROWB + kt * 32, b0, b1, b2, b3);
                ldsm4(wH + bOff + (u32)((2*pp+1) * 16) * ROWB + kt * 32, c0, c1, c2, c3);
                mmah(acc[4*pp],           h00, h01, h02, h03, b0, b1);
                mmah(acc[4*pp + 1],       h00, h01, h02, h03, b2, b3);
                mmah(acc[NTL + 4*pp],     h10, h11, h12, h13, b0, b1);
                mmah(acc[NTL + 4*pp + 1], h10, h11, h12, h13, b2, b3);
                mmah(acc[4*pp + 2],       h00, h01, h02, h03, c0, c1);
                mmah(acc[4*pp + 3],       h00, h01, h02, h03, c2, c3);
                mmah(acc[NTL + 4*pp + 2], h10, h11, h12, h13, c0, c1);
                mmah(acc[NTL + 4*pp + 3], h10, h11, h12, h13, c2, c3);
            }
        } else {
#pragma unroll
            for (int p = 0; p < NTL / 2; ++p) {
                u32 b0, b1, b2, b3;
                ldsm4(wH + bOff + (u32)(p * 16) * ROWB + kt * 32, b0, b1, b2, b3);
                mmah(acc[2*p],           h00, h01, h02, h03, b0, b1);
                mmah(acc[2*p + 1],       h00, h01, h02, h03, b2, b3);
                mmah(acc[NTL + 2*p],     h10, h11, h12, h13, b0, b1);
                mmah(acc[NTL + 2*p + 1], h10, h11, h12, h13, b2, b3);
            }
        }
    }
}

// Epilogue: bias + relu, write back as single-fp16 rows.
template<int NTL>
__device__ __forceinline__ void epi_f16(const float (*acc)[4], const float* bias,
                                        char* smc, int lane, int warp) {
    const int r0 = warp * 32 + (lane >> 2);
    const int cb = (lane & 3) * 2;
#pragma unroll
    for (int mt = 0; mt < 2; ++mt) {
#pragma unroll
        for (int nt = 0; nt < NTL; ++nt) {
            const int c = 8 * nt + cb;
            const float b0 = bias[c], b1 = bias[c + 1];
            const float* a = acc[mt * NTL + nt];
            float v0 = fmaxf(a[0] + b0, 0.f), v1 = fmaxf(a[1] + b1, 0.f);
            float v2 = fmaxf(a[2] + b0, 0.f), v3 = fmaxf(a[3] + b1, 0.f);
            const int rA = r0 + 16 * mt, rB = rA + 8;
            *(u32*)(smc + SM_AH + rA * ROWB + c * 2) = pk2h(v0, v1);
            *(u32*)(smc + SM_AH + rB * ROWB + c * 2) = pk2h(v2, v3);
        }
    }
}

// Write one activation row (nch chunks of 8 cols) as single-fp16.
__device__ __forceinline__ void write_row(char* smc, int s, const float* v, int nch) {
    for (int ch = 0; ch < nch; ++ch) {
        u32 h[4];
#pragma unroll
        for (int q = 0; q < 4; ++q)
            h[q] = pk2h(v[8 * ch + 2 * q], v[8 * ch + 2 * q + 1]);
        *(uint4*)(smc + SM_AH + s * ROWB + ch * 16) = make_uint4(h[0], h[1], h[2], h[3]);
    }
}

// fp32 W[k][n] (global) -> smem [n][72] fp16, K padded to 64.
__device__ void prep_B(char* smc, const float* W, int Kreal, int Nrows, int stride,
                       int offH) {
    for (int idx = threadIdx.x; idx < Nrows * 64; idx += NT) {
        int nr = idx >> 6, k = idx & 63;
        float x = (k < Kreal) ? __ldg(W + k * stride + nr) : 0.0f;
        u32 p = pk2h(x, x);
        *(unsigned short*)(smc + offH + nr * ROWB + k * 2) = (unsigned short)(p & 0xffffu);
    }
}

// Color-L1 weights with the dir-MLP second layer folded in (R12 ordering):
//   rows 0..14 : cw1 (geo); rows 15..30 : rw2 @ cw1[15:31]; rows 31..62 : cw1 (app)
__device__ void prep_CW1_folded(char* smc, const float* cw1, const float* rw2,
                                int offH) {
    for (int idx = threadIdx.x; idx < 64 * 64; idx += NT) {
        int nr = idx >> 6, k = idx & 63;
        float x;
        if (k < 15) {
            x = __ldg(cw1 + k * 64 + nr);
        } else if (k < 31) {
            const int t = k - 15;
            float s = 0.0f;
#pragma unroll
            for (int j = 0; j < 16; ++j)
                s = fmaf(__ldg(rw2 + t * 16 + j), __ldg(cw1 + (15 + j) * 64 + nr), s);
            x = s;
        } else if (k < 63) {
            x = __ldg(cw1 + k * 64 + nr);
        } else {
            x = 0.0f;
        }
        u32 p = pk2h(x, x);
        *(unsigned short*)(smc + offH + nr * ROWB + k * 2) = (unsigned short)(p & 0xffffu);
    }
}

__device__ void cpyf(char* smc, int off, const float* src, int nf) {
    float* d = (float*)(smc + off);
    for (int t = threadIdx.x; t < nf; t += NT) d[t] = __ldg(src + t);
}

struct ResArr { int r[16]; };

__global__ void __launch_bounds__(NT, 1) nerf_h12_kernel(
    const float* __restrict__ rs, const float* __restrict__ dirs,
    const int*   __restrict__ cam, const float* __restrict__ aabb,
    const float* __restrict__ ht,
    const float* __restrict__ rw1, const float* __restrict__ rb1,
    const float* __restrict__ rw2, const float* __restrict__ rb2,
    const float* __restrict__ dw1, const float* __restrict__ db1,
    const float* __restrict__ dw2, const float* __restrict__ db2,
    const float* __restrict__ dw3, const float* __restrict__ db3,
    const float* __restrict__ cw1, const float* __restrict__ cb1,
    const float* __restrict__ cw2, const float* __restrict__ cb2,
    const float* __restrict__ cw3, const float* __restrict__ cb3,
    const float* __restrict__ app,
    float* __restrict__ out, int n, ResArr RA)
{
    extern __shared__ __align__(128) char smc[];
    u32 sb;
    asm("{ .reg .u64 t; cvta.to.shared.u64 t, %1; cvt.u32.u64 %0, t; }"
        : "=r"(sb) : "l"(smc));

    prep_B(smc, dw1, 32, 64, 64, SM_WD1H);
    prep_B(smc, dw2, 64, 64, 64, SM_WD2H);
    prep_B(smc, dw3, 64, 16, 16, SM_WD3H);
    prep_CW1_folded(smc, cw1, rw2, SM_WC1H);
    prep_B(smc, cw2, 64, 64, 64, SM_WC2H);
    cpyf(smc, SM_DB1, db1, 64);  cpyf(smc, SM_DB2, db2, 64);
    cpyf(smc, SM_DB3, db3, 16);
    // cb1' = cb1 + rb2 @ cw1[15:31]
    if (threadIdx.x < 64) {
        const int t = threadIdx.x;
        float s = __ldg(cb1 + t);
#pragma unroll
        for (int j = 0; j < 16; ++j)
            s = fmaf(__ldg(rb2 + j), __ldg(cw1 + (15 + j) * 64 + t), s);
        ((float*)(smc + SM_CB1))[t] = s;
    }
    cpyf(smc, SM_CB2, cb2, 64);  cpyf(smc, SM_CB3, cb3, 3);
    cpyf(smc, SM_RW1, rw1, 48);  cpyf(smc, SM_RB1, rb1, 16);
    cpyf(smc, SM_CW3, cw3, 192);
    __syncthreads();

    const int tid = threadIdx.x, lane = tid & 31, warp = tid >> 5;
    const u32 AHu = sb + SM_AH;

    const float a0x = __ldg(aabb + 0), a0y = __ldg(aabb + 1), a0z = __ldg(aabb + 2);
    const float ddx = __ldg(aabb + 3) - a0x;
    const float ddy = __ldg(aabb + 4) - a0y;
    const float ddz = __ldg(aabb + 5) - a0z;
    const float2* htp = (const float2*)ht;
    const float* sDB1 = (const float*)(smc + SM_DB1);
    const float* sDB2 = (const float*)(smc + SM_DB2);
    const float* sDB3 = (const float*)(smc + SM_DB3);
    const float* sCB1 = (const float*)(smc + SM_CB1);
    const float* sCB2 = (const float*)(smc + SM_CB2);
    const float* sCB3 = (const float*)(smc + SM_CB3);
    const float* sRW1 = (const float*)(smc + SM_RW1);
    const float* sRB1 = (const float*)(smc + SM_RB1);
    const float* sCW3 = (const float*)(smc + SM_CW3);
    float* sOUT = (float*)(smc + SM_OUT);

    const int ntiles = (n + TS - 1) / TS;

    for (int tile = blockIdx.x; tile < ntiles; tile += gridDim.x) {
        const int i0 = tile * TS;
        int i = i0 + tid; if (i >= n) i = n - 1;

        const int   ci  = __ldg(cam + i);
        const float dvx = __ldg(dirs + 3*i + 0);
        const float dvy = __ldg(dirs + 3*i + 1);
        const float dvz = __ldg(dirs + 3*i + 2);

        // ---- hash encode (exact fp32) -> A row (32 cols, fp16) ----
        {
            float ev[32];
            const float px = fminf(fmaxf((__ldg(rs + 3*i + 0) - a0x) / ddx, 0.f), 1.f);
            const float py = fminf(fmaxf((__ldg(rs + 3*i + 1) - a0y) / ddy, 0.f), 1.f);
            const float pz = fminf(fmaxf((__ldg(rs + 3*i + 2) - a0z) / ddz, 0.f), 1.f);
#pragma unroll
            for (int l = 0; l < 16; ++l) {
                const int r = RA.r[l];
                const float rf = (float)(r - 1);
                int cx = (int)floorf(px * rf);
                int cy = (int)floorf(py * rf);
                int cz = (int)floorf(pz * rf);
                cx = min(max(cx, 0), r - 1);
                cy = min(max(cy, 0), r - 1);
                cz = min(max(cz, 0), r - 1);
                const unsigned h = ((unsigned)cx + (unsigned)cy * 2481u
                                    + (unsigned)cz * 1941u) & 4095u;
                const float2 f = __ldg(htp + l * 4096 + h);
                ev[2*l] = f.x; ev[2*l + 1] = f.y;
            }
            write_row(smc, tid, ev, 4);
        }
        __syncwarp();

        float acc[16][4];
        // ---- density L1 (K=32) ----
        do_gemm<2, 8>(AHu, sb + SM_WD1H, lane, warp, acc);
        __syncwarp();
        epi_f16<8>(acc, sDB1, smc, lane, warp);
        __syncwarp();
        // ---- density L2 (K=64) ----
        do_gemm<4, 8>(AHu, sb + SM_WD2H, lane, warp, acc);
        __syncwarp();
        epi_f16<8>(acc, sDB2, smc, lane, warp);
        __syncwarp();
        // ---- density L3 (64 -> 16) -> sOUT cols 3..18 (raw dfeat) ----
        do_gemm<4, 2>(AHu, sb + SM_WD3H, lane, warp, acc);
        __syncwarp();
        {
            const int cb = (lane & 3) * 2;
#pragma unroll
            for (int mt = 0; mt < 2; ++mt)
#pragma unroll
                for (int nt = 0; nt < 2; ++nt) {
                    const int c = 8 * nt + cb;
                    const float b0 = sDB3[c], b1 = sDB3[c + 1];
                    const float* a = acc[mt * 2 + nt];
                    const int rA = warp * 32 + 16 * mt + (lane >> 2), rB = rA + 8;
                    sOUT[rA * 19 + 3 + c] = a[0] + b0;
                    sOUT[rA * 19 + 4 + c] = a[1] + b1;
                    sOUT[rB * 19 + 3 + c] = a[2] + b0;
                    sOUT[rB * 19 + 4 + c] = a[3] + b1;
                }
        }
        __syncwarp();

        // ---- cin build (single-fp16 plane) ----
        float df0;
        {
            float4 ap[8];
            const float4* a4 = (const float4*)(app + (size_t)ci * 32);
#pragma unroll
            for (int q = 0; q < 8; ++q) ap[q] = __ldg(a4 + q);

            const float* drow = sOUT + (warp * 32 + lane) * 19 + 3;
            float cin[64];
            df0 = drow[0];
#pragma unroll
            for (int j = 0; j < 15; ++j) cin[j] = drow[1 + j];
            const float dv[3] = { dvx, dvy, dvz };
#pragma unroll
            for (int j = 0; j < 16; ++j) {
                float a = sRB1[j];
#pragma unroll
                for (int k = 0; k < 3; ++k)
                    a = fmaf(dv[k], sRW1[k*16 + j], a);
                cin[15 + j] = fmaxf(a, 0.0f);
            }
#pragma unroll
            for (int q = 0; q < 8; ++q) {
                cin[31 + 4*q + 0] = ap[q].x; cin[31 + 4*q + 1] = ap[q].y;
                cin[31 + 4*q + 2] = ap[q].z; cin[31 + 4*q + 3] = ap[q].w;
            }
            cin[63] = 0.0f;
            write_row(smc, tid, cin, 8);
        }
        __syncwarp();
        // ---- color L1 (K=64, folded weights, cb1') ----
        do_gemm<4, 8>(AHu, sb + SM_WC1H, lane, warp, acc);
        __syncwarp();
        epi_f16<8>(acc, sCB1, smc, lane, warp);
        __syncwarp();
        // ---- color L2 (K=64); final 64->3 from accumulators ----
        do_gemm<4, 8>(AHu, sb + SM_WC2H, lane, warp, acc);
        __syncwarp();
        {
            const int cb = (lane & 3) * 2;
#pragma unroll
            for (int mt = 0; mt < 2; ++mt)
#pragma unroll
                for (int nt = 0; nt < 8; ++nt) {
                    const int c = 8 * nt + cb;
                    float* a = acc[mt * 8 + nt];
                    a[0] = fmaxf(a[0] + sCB2[c], 0.f);
                    a[1] = fmaxf(a[1] + sCB2[c + 1], 0.f);
                    a[2] = fmaxf(a[2] + sCB2[c], 0.f);
                    a[3] = fmaxf(a[3] + sCB2[c + 1], 0.f);
                }
            float w3[8][2][3];
#pragma unroll
            for (int nt = 0; nt < 8; ++nt)
#pragma unroll
                for (int e = 0; e < 2; ++e) {
                    const int c = 8 * nt + cb + e;
#pragma unroll
                    for (int j = 0; j < 3; ++j) w3[nt][e][j] = sCW3[c * 3 + j];
                }
            float s[4][3];
#pragma unroll
            for (int v = 0; v < 4; ++v)
#pragma unroll
                for (int j = 0; j < 3; ++j) s[v][j] = 0.f;
#pragma unroll
            for (int mt = 0; mt < 2; ++mt)
#pragma unroll
                for (int h = 0; h < 2; ++h)
#pragma unroll
                    for (int nt = 0; nt < 8; ++nt)
#pragma unroll
                        for (int e = 0; e < 2; ++e) {
                            const float x = acc[mt * 8 + nt][2 * h + e];
#pragma unroll
                            for (int j = 0; j < 3; ++j)
                                s[mt * 2 + h][j] = fmaf(x, w3[nt][e][j],
                                                        s[mt * 2 + h][j]);
                        }
#pragma unroll
            for (int v = 0; v < 4; ++v)
#pragma unroll
                for (int j = 0; j < 3; ++j) {
                    s[v][j] += __shfl_xor_sync(0xffffffffu, s[v][j], 1);
                    s[v][j] += __shfl_xor_sync(0xffffffffu, s[v][j], 2);
                }
            const int q = lane & 3;
            const int row = warp * 32 + 16 * (q >> 1) + 8 * (q & 1) + (lane >> 2);
            const float r0 = s[q][0], r1 = s[q][1], r2 = s[q][2];
            sOUT[row * 19 + 0] = 1.0f / (1.0f + expf(-(r0 + sCB3[0])));
            sOUT[row * 19 + 1] = 1.0f / (1.0f + expf(-(r1 + sCB3[1])));
            sOUT[row * 19 + 2] = 1.0f / (1.0f + expf(-(r2 + sCB3[2])));
            sOUT[(warp * 32 + lane) * 19 + 3] = fmaxf(df0, 0.0f);
        }
        __syncwarp();
        // ---- linear coalesced store ----
        {
            const int m = min(TS, n - i0);
            const int vw = min(32, m - warp * 32);
            if (vw > 0) {
                float* gbase = out + (size_t)(i0 + warp * 32) * 19;
                const float* sbase = sOUT + (warp * 32) * 19;
                if (vw == 32) {
                    const float4* s4 = (const float4*)sbase;
                    float4* g4 = (float4*)gbase;
#pragma unroll
                    for (int j = 0; j < 5; ++j) {
                        int idx = lane + j * 32;
                        if (idx < 152) g4[idx] = s4[idx];
                    }
                } else {
                    for (int j = lane; j < vw * 19; j += 32) gbase[j] = sbase[j];
                }
            }
        }
        __syncwarp();
    }
}

extern "C" void kernel_launch(void* const* d_in, const int* in_sizes, int n_in,
                              void* d_out, int out_size) {
    const float* rs   = (const float*)d_in[0];
    const float* dirs = (const float*)d_in[1];
    const int*   cam  = (const int*)d_in[2];
    const float* aabb = (const float*)d_in[3];
    const float* ht   = (const float*)d_in[4];
    const float* rw1  = (const float*)d_in[5];
    const float* rb1  = (const float*)d_in[6];
    const float* rw2  = (const float*)d_in[7];
    const float* rb2  = (const float*)d_in[8];
    const float* dw1  = (const float*)d_in[9];
    const float* db1  = (const float*)d_in[10];
    const float* dw2  = (const float*)d_in[11];
    const float* db2  = (const float*)d_in[12];
    const float* dw3  = (const float*)d_in[13];
    const float* db3  = (const float*)d_in[14];
    const float* cw1  = (const float*)d_in[15];
    const float* cb1  = (const float*)d_in[16];
    const float* cw2  = (const float*)d_in[17];
    const float* cb2  = (const float*)d_in[18];
    const float* cw3  = (const float*)d_in[19];
    const float* cb3  = (const float*)d_in[20];
    const float* app  = (const float*)d_in[21];
    float* out = (float*)d_out;

    const int n = in_sizes[0] / 3;

    ResArr ra;
    double growth = exp((log(2048.0) - log(16.0)) / 15.0);
    for (int i = 0; i < 16; ++i)
        ra.r[i] = (int)(16.0 * pow(growth, (double)i));

    cudaFuncSetAttribute(nerf_h12_kernel,
                         cudaFuncAttributeMaxDynamicSharedMemorySize, SMEM_BYTES);

    dim3 grid(148), block(NT);   // 1 CTA/SM persistent, 12 warps, warp-independent
    nerf_h12_kernel<<<grid, block, SMEM_BYTES>>>(
        rs, dirs, cam, aabb, ht,
        rw1, rb1, rw2, rb2,
        dw1, db1, dw2, db2, dw3, db3,
        cw1, cb1, cw2, cb2, cw3, cb3,
        app, out, n, ra);
}